// round 3
// baseline (speedup 1.0000x reference)
#include <cuda_runtime.h>
#include <math.h>
#include <stdint.h>

#define BB 32
#define TT 64
#define SS 64
#define HH 1024
#define EE 512
#define VV 32000
#define G4H 4096
#define NBLK 128

// ---------------- device scratch ----------------
__device__ float g_gi[TT * BB * G4H];     // x@W_ih^T + b_ih + b_hh (32MB)
__device__ float g_h[2][BB * HH];
__device__ float g_c[BB * HH];
__device__ float g_sc[BB * SS];           // raw attention scores
__device__ float g_P[SS * BB * HH];       // hiddens . fc1W_ctx  (8MB)
__device__ float g_barout[TT * BB * HH];  // tanh(fc1) rows m=t*B+b (8MB)

// grid barrier state (generation counter; monotonic across graph replays)
__device__ unsigned g_bar_count;
__device__ volatile unsigned g_bar_gen;

__device__ __forceinline__ void grid_sync() {
    __syncthreads();
    if (threadIdx.x == 0) {
        unsigned gen = g_bar_gen;
        __threadfence();
        if (atomicInc(&g_bar_count, NBLK - 1) == NBLK - 1) {
            g_bar_gen = gen + 1;
        } else {
            while (g_bar_gen == gen) { __nanosleep(40); }
        }
        __threadfence();
    }
    __syncthreads();
}

// ---------------- GEMM1: gi = emb[vid] @ W_ih^T + b_ih + b_hh ----------------
__global__ void embed_gemm(const int* __restrict__ inputs, const float* __restrict__ emb,
                           const float* __restrict__ W, const float* __restrict__ b1,
                           const float* __restrict__ b2) {
    __shared__ float As[16][128];
    __shared__ float Bs[16][128];
    __shared__ int vid[128];
    const int tid = threadIdx.x;
    const int mBase = blockIdx.y * 128, nBase = blockIdx.x * 128;
    if (tid < 128) {
        int m = mBase + tid;
        vid[tid] = inputs[(m & 31) * TT + (m >> 5)];
    }
    const int tx = tid & 15, ty = tid >> 4;
    const int lrow = tid >> 1, lcol = (tid & 1) * 8;
    float acc[8][8] = {};
    __syncthreads();
    const float* aSrc = emb + (long)vid[lrow] * EE + lcol;
    const float* bSrc = W + (long)(nBase + lrow) * EE + lcol;
    for (int k0 = 0; k0 < EE; k0 += 16) {
        float4 a0 = *(const float4*)(aSrc + k0);
        float4 a1 = *(const float4*)(aSrc + k0 + 4);
        float4 w0 = *(const float4*)(bSrc + k0);
        float4 w1 = *(const float4*)(bSrc + k0 + 4);
        As[lcol + 0][lrow] = a0.x; As[lcol + 1][lrow] = a0.y;
        As[lcol + 2][lrow] = a0.z; As[lcol + 3][lrow] = a0.w;
        As[lcol + 4][lrow] = a1.x; As[lcol + 5][lrow] = a1.y;
        As[lcol + 6][lrow] = a1.z; As[lcol + 7][lrow] = a1.w;
        Bs[lcol + 0][lrow] = w0.x; Bs[lcol + 1][lrow] = w0.y;
        Bs[lcol + 2][lrow] = w0.z; Bs[lcol + 3][lrow] = w0.w;
        Bs[lcol + 4][lrow] = w1.x; Bs[lcol + 5][lrow] = w1.y;
        Bs[lcol + 6][lrow] = w1.z; Bs[lcol + 7][lrow] = w1.w;
        __syncthreads();
#pragma unroll
        for (int k = 0; k < 16; k++) {
            float a[8], bv[8];
            *(float4*)&a[0] = *(const float4*)&As[k][ty * 8];
            *(float4*)&a[4] = *(const float4*)&As[k][ty * 8 + 4];
            *(float4*)&bv[0] = *(const float4*)&Bs[k][tx * 8];
            *(float4*)&bv[4] = *(const float4*)&Bs[k][tx * 8 + 4];
#pragma unroll
            for (int i = 0; i < 8; i++)
#pragma unroll
                for (int j = 0; j < 8; j++) acc[i][j] += a[i] * bv[j];
        }
        __syncthreads();
    }
#pragma unroll
    for (int i = 0; i < 8; i++) {
        int m = mBase + ty * 8 + i;
        float* o = g_gi + (long)m * G4H + nBase + tx * 8;
#pragma unroll
        for (int j = 0; j < 8; j++) {
            int n = nBase + tx * 8 + j;
            o[j] = acc[i][j] + b1[n] + b2[n];
        }
    }
}

// ---------------- P gemm: P[s*32+b][j] = hiddens[s][b][:] . fc1_W[j][1024:2048] ----
// M=2048 (rows of hiddens, contiguous), N=1024, K=1024.
__global__ void p_gemm(const float* __restrict__ hiddens, const float* __restrict__ W) {
    __shared__ float As[16][128];
    __shared__ float Bs[16][128];
    const int tid = threadIdx.x;
    const int mBase = blockIdx.y * 128, nBase = blockIdx.x * 128;
    const int tx = tid & 15, ty = tid >> 4;
    const int lrow = tid >> 1, lcol = (tid & 1) * 8;
    float acc[8][8] = {};
    const float* aSrc = hiddens + (long)(mBase + lrow) * HH + lcol;
    const float* bSrc = W + (long)(nBase + lrow) * 2048 + 1024 + lcol;
    for (int k0 = 0; k0 < HH; k0 += 16) {
        float4 a0 = *(const float4*)(aSrc + k0);
        float4 a1 = *(const float4*)(aSrc + k0 + 4);
        float4 w0 = *(const float4*)(bSrc + k0);
        float4 w1 = *(const float4*)(bSrc + k0 + 4);
        As[lcol + 0][lrow] = a0.x; As[lcol + 1][lrow] = a0.y;
        As[lcol + 2][lrow] = a0.z; As[lcol + 3][lrow] = a0.w;
        As[lcol + 4][lrow] = a1.x; As[lcol + 5][lrow] = a1.y;
        As[lcol + 6][lrow] = a1.z; As[lcol + 7][lrow] = a1.w;
        Bs[lcol + 0][lrow] = w0.x; Bs[lcol + 1][lrow] = w0.y;
        Bs[lcol + 2][lrow] = w0.z; Bs[lcol + 3][lrow] = w0.w;
        Bs[lcol + 4][lrow] = w1.x; Bs[lcol + 5][lrow] = w1.y;
        Bs[lcol + 6][lrow] = w1.z; Bs[lcol + 7][lrow] = w1.w;
        __syncthreads();
#pragma unroll
        for (int k = 0; k < 16; k++) {
            float a[8], bv[8];
            *(float4*)&a[0] = *(const float4*)&As[k][ty * 8];
            *(float4*)&a[4] = *(const float4*)&As[k][ty * 8 + 4];
            *(float4*)&bv[0] = *(const float4*)&Bs[k][tx * 8];
            *(float4*)&bv[4] = *(const float4*)&Bs[k][tx * 8 + 4];
#pragma unroll
            for (int i = 0; i < 8; i++)
#pragma unroll
                for (int j = 0; j < 8; j++) acc[i][j] += a[i] * bv[j];
        }
        __syncthreads();
    }
#pragma unroll
    for (int i = 0; i < 8; i++) {
        int m = mBase + ty * 8 + i;
        float* o = g_P + (long)m * HH + nBase + tx * 8;
#pragma unroll
        for (int j = 0; j < 8; j++) o[j] = acc[i][j];
    }
}

// ---------------- persistent recurrence: 128 blocks x 256 threads ----------------
__global__ void __launch_bounds__(256) recurrent(
    const float* __restrict__ hiddens, const float* __restrict__ h0,
    const float* __restrict__ c0, const float* __restrict__ Whh,
    const float* __restrict__ fc1W, const float* __restrict__ fc1b)
{
    __shared__ float sbuf[11776];   // 46 KB, carved per phase
    const int tid = threadIdx.x;
    const int bi = blockIdx.x;
    const int w = tid >> 5, lane = tid & 31;
    const int bl = lane & 7, kfl = lane >> 3;

    // init h, c
    {
        int i = bi * 256 + tid;
        g_h[0][i] = h0[i];
        g_c[i] = c0[i];
    }
    grid_sync();

    const int jbase = bi * 8;   // this block's 8 hidden indices (phases A and C)

    for (int t = 0; t < TT; t++) {
        const float* __restrict__ hin = g_h[t & 1];
        float* __restrict__ hout = g_h[(t + 1) & 1];

        // ============ Phase A: gates = hin @ Whh^T + gi[t]; pointwise -> hout, c ====
        {
            float* Hs = sbuf;           // [128][36] k-major
            float* Ws = sbuf + 4608;    // [128][36]
            const int kq = tid >> 5;            // 8 k-quarters (== warp)
            const int cq = (tid >> 3) & 3;      // 4
            const int bq = tid & 7;             // 8
            const int b0 = bq * 4, c0i = cq * 8;
            float acc[4][8] = {};
            for (int k0 = 0; k0 < HH; k0 += 128) {
#pragma unroll
                for (int i = 0; i < 4; i++) {
                    int grp = i * 8 + w;                 // 0..31
                    int bb = (grp & 3) * 8 + bl;
                    int kf = (grp >> 2) * 4 + kfl;
                    float4 v = *(const float4*)&hin[bb * HH + k0 + kf * 4];
                    Hs[(kf * 4 + 0) * 36 + bb] = v.x;
                    Hs[(kf * 4 + 1) * 36 + bb] = v.y;
                    Hs[(kf * 4 + 2) * 36 + bb] = v.z;
                    Hs[(kf * 4 + 3) * 36 + bb] = v.w;
                    int cc = bb;
                    int row = (cc >> 3) * HH + jbase + (cc & 7);
                    float4 wv = *(const float4*)&Whh[row * HH + k0 + kf * 4];
                    Ws[(kf * 4 + 0) * 36 + cc] = wv.x;
                    Ws[(kf * 4 + 1) * 36 + cc] = wv.y;
                    Ws[(kf * 4 + 2) * 36 + cc] = wv.z;
                    Ws[(kf * 4 + 3) * 36 + cc] = wv.w;
                }
                __syncthreads();
#pragma unroll
                for (int kk = 0; kk < 16; kk++) {
                    int k = kq * 16 + kk;
                    float4 h4 = *(const float4*)&Hs[k * 36 + b0];
                    float4 wlo = *(const float4*)&Ws[k * 36 + c0i];
                    float4 whi = *(const float4*)&Ws[k * 36 + c0i + 4];
                    float hv[4] = {h4.x, h4.y, h4.z, h4.w};
                    float wv[8] = {wlo.x, wlo.y, wlo.z, wlo.w, whi.x, whi.y, whi.z, whi.w};
#pragma unroll
                    for (int i = 0; i < 4; i++)
#pragma unroll
                        for (int j = 0; j < 8; j++) acc[i][j] += hv[i] * wv[j];
                }
                __syncthreads();
            }
            // reduce 8 k-quarters via smem slab (aliases Hs/Ws after sync)
            float* Red = sbuf;   // [8][32][32]
#pragma unroll
            for (int i = 0; i < 4; i++)
#pragma unroll
                for (int j = 0; j < 8; j++)
                    Red[kq * 1024 + (b0 + i) * 32 + c0i + j] = acc[i][j];
            __syncthreads();
            // pointwise: thread = (b, jl)
            {
                int b = tid >> 3, jl = tid & 7;
                const float* gr = g_gi + (long)(t * BB + b) * G4H;
                float g4[4];
#pragma unroll
                for (int g = 0; g < 4; g++) {
                    float s = 0.f;
#pragma unroll
                    for (int q = 0; q < 8; q++) s += Red[q * 1024 + b * 32 + g * 8 + jl];
                    g4[g] = s + gr[g * HH + jbase + jl];
                }
                float ig = 1.f / (1.f + expf(-g4[0]));
                float fg = 1.f / (1.f + expf(-g4[1]));
                float gg = tanhf(g4[2]);
                float og = 1.f / (1.f + expf(-g4[3]));
                int j = jbase + jl;
                float cn = fg * g_c[b * HH + j] + ig * gg;
                g_c[b * HH + j] = cn;
                hout[b * HH + j] = og * tanhf(cn);
            }
        }
        grid_sync();

        // ============ Phase B: scores[b][s] = hout[b] . hiddens[s][b] =============
        {
            float* hsh = sbuf;
            int b = bi >> 2, sq = bi & 3;
            *(float4*)&hsh[tid * 4] = *(const float4*)&hout[b * HH + tid * 4];
            __syncthreads();
#pragma unroll
            for (int si = 0; si < 2; si++) {
                int s = sq * 16 + w * 2 + si;
                const float* e = hiddens + ((long)s * BB + b) * HH;
                float a = 0.f;
#pragma unroll
                for (int r = 0; r < 8; r++) {
                    float4 ev = *(const float4*)&e[lane * 4 + r * 128];
                    float4 h4 = *(const float4*)&hsh[lane * 4 + r * 128];
                    a += ev.x * h4.x + ev.y * h4.y + ev.z * h4.z + ev.w * h4.w;
                }
                for (int o = 16; o; o >>= 1) a += __shfl_down_sync(0xFFFFFFFFu, a, o);
                if (!lane) g_sc[b * SS + s] = a;
            }
        }
        grid_sync();

        // ============ Phase C: softmax + fc1(h-part GEMM + P-part) + tanh =========
        {
            float* sm_a = sbuf;          // [32][64]
            float* Hs = sbuf + 2048;     // [128][36]
            float* Ws = sbuf + 6656;     // [128][12]
            float* RedC = sbuf + 8192;   // [8][32][8]
            // softmax (8 warps x 4 b-rows)
#pragma unroll
            for (int r = 0; r < 4; r++) {
                int b = w * 4 + r;
                float v0 = g_sc[b * SS + lane];
                float v1 = g_sc[b * SS + 32 + lane];
                float m = fmaxf(v0, v1);
                for (int o = 16; o; o >>= 1) m = fmaxf(m, __shfl_xor_sync(0xFFFFFFFFu, m, o));
                float e0 = expf(v0 - m), e1 = expf(v1 - m);
                float s = e0 + e1;
                for (int o = 16; o; o >>= 1) s += __shfl_xor_sync(0xFFFFFFFFu, s, o);
                float inv = 1.f / s;
                sm_a[b * SS + lane] = e0 * inv;
                sm_a[b * SS + 32 + lane] = e1 * inv;
            }
            __syncthreads();
            // h-part GEMM: 32b x 8j, K=1024, k split 8 ways
            const int kq = tid >> 5;
            const int jq = (tid >> 3) & 3;
            const int bq = tid & 7;
            const int b0 = bq * 4, j0 = jq * 2;
            float acc[4][2] = {};
            for (int k0 = 0; k0 < HH; k0 += 128) {
#pragma unroll
                for (int i = 0; i < 4; i++) {
                    int grp = i * 8 + w;
                    int bb = (grp & 3) * 8 + bl;
                    int kf = (grp >> 2) * 4 + kfl;
                    float4 v = *(const float4*)&hout[bb * HH + k0 + kf * 4];
                    Hs[(kf * 4 + 0) * 36 + bb] = v.x;
                    Hs[(kf * 4 + 1) * 36 + bb] = v.y;
                    Hs[(kf * 4 + 2) * 36 + bb] = v.z;
                    Hs[(kf * 4 + 3) * 36 + bb] = v.w;
                }
#pragma unroll
                for (int i = 0; i < 4; i++) {
                    int v = tid + i * 256;
                    int jl = v >> 7, k = v & 127;
                    Ws[k * 12 + jl] = fc1W[(jbase + jl) * 2048 + k0 + k];
                }
                __syncthreads();
#pragma unroll
                for (int kk = 0; kk < 16; kk++) {
                    int k = kq * 16 + kk;
                    float4 h4 = *(const float4*)&Hs[k * 36 + b0];
                    float2 w2 = *(const float2*)&Ws[k * 12 + j0];
                    float hv[4] = {h4.x, h4.y, h4.z, h4.w};
#pragma unroll
                    for (int i = 0; i < 4; i++) {
                        acc[i][0] += hv[i] * w2.x;
                        acc[i][1] += hv[i] * w2.y;
                    }
                }
                __syncthreads();
            }
#pragma unroll
            for (int i = 0; i < 4; i++) {
                RedC[kq * 256 + (b0 + i) * 8 + j0] = acc[i][0];
                RedC[kq * 256 + (b0 + i) * 8 + j0 + 1] = acc[i][1];
            }
            __syncthreads();
            // per-output: sum partials + P-part + tanh
            {
                int b = tid >> 3, jl = tid & 7;
                float v = fc1b[jbase + jl];
#pragma unroll
                for (int q = 0; q < 8; q++) v += RedC[q * 256 + b * 8 + jl];
                const float* Pp = g_P + b * HH + jbase + jl;
#pragma unroll 8
                for (int s = 0; s < SS; s++)
                    v += sm_a[b * SS + s] * Pp[(long)s * BB * HH];
                g_barout[(long)(t * BB + b) * HH + jbase + jl] = tanhf(v);
            }
        }
        grid_sync();
    }
}

// ---------------- fc2: tf32 mma.sync GEMM. M=2048, N=32000, K=1024 ----------------
__device__ __forceinline__ uint32_t f2tf(float x) {
    uint32_t r;
    asm("cvt.rna.tf32.f32 %0, %1;" : "=r"(r) : "f"(x));
    return r;
}
__device__ __forceinline__ void mma_tf32(float* c, const uint32_t* a, const uint32_t* b) {
    asm volatile(
        "mma.sync.aligned.m16n8k8.row.col.f32.tf32.tf32.f32 "
        "{%0,%1,%2,%3},{%4,%5,%6,%7},{%8,%9},{%0,%1,%2,%3};"
        : "+f"(c[0]), "+f"(c[1]), "+f"(c[2]), "+f"(c[3])
        : "r"(a[0]), "r"(a[1]), "r"(a[2]), "r"(a[3]), "r"(b[0]), "r"(b[1]));
}

__global__ void __launch_bounds__(256) fc2_mma(const float* __restrict__ Wt,
                                               const float* __restrict__ bias,
                                               float* __restrict__ out) {
    extern __shared__ float smem[];
    float* As = smem;            // [2buf][2ks][128][12]
    float* Bs = smem + 6144;     // [2buf][2ks][256][12]
    const int tid = threadIdx.x;
    const int wid = tid >> 5, lane = tid & 31;
    const int g = lane >> 2, kq = lane & 3;
    const int mBase = blockIdx.y * 128;
    const int nBase = blockIdx.x * 256;
    const int warpM = (wid & 1) * 64;
    const int warpN = (wid >> 1) * 64;

    float acc[4][8][4];
#pragma unroll
    for (int i = 0; i < 4; i++)
#pragma unroll
        for (int j = 0; j < 8; j++)
#pragma unroll
            for (int k = 0; k < 4; k++) acc[i][j][k] = 0.f;

    float bc0[8], bc1[8];
#pragma unroll
    for (int nf = 0; nf < 8; nf++) {
        int col = nBase + warpN + nf * 8 + kq * 2;
        bc0[nf] = bias[col]; bc1[nf] = bias[col + 1];
    }

    const int arow = tid >> 2, aq = tid & 3;
    {
#pragma unroll
        for (int i = 0; i < 2; i++) {
            float4 v = *(const float4*)&g_barout[(long)(mBase + arow + i * 64) * HH + aq * 4];
            float* d = &As[((0 * 2 + (aq >> 1)) * 128 + arow + i * 64) * 12 + (aq & 1) * 4];
            d[0] = __uint_as_float(f2tf(v.x)); d[1] = __uint_as_float(f2tf(v.y));
            d[2] = __uint_as_float(f2tf(v.z)); d[3] = __uint_as_float(f2tf(v.w));
        }
#pragma unroll
        for (int i = 0; i < 4; i++) {
            float4 v = *(const float4*)&Wt[(long)(nBase + arow + i * 64) * HH + aq * 4];
            float* d = &Bs[((0 * 2 + (aq >> 1)) * 256 + arow + i * 64) * 12 + (aq & 1) * 4];
            d[0] = __uint_as_float(f2tf(v.x)); d[1] = __uint_as_float(f2tf(v.y));
            d[2] = __uint_as_float(f2tf(v.z)); d[3] = __uint_as_float(f2tf(v.w));
        }
    }
    __syncthreads();

    float4 ra[2], rb[4];
    for (int kt = 0; kt < 64; kt++) {
        const int cur = kt & 1;
        if (kt < 63) {
#pragma unroll
            for (int i = 0; i < 2; i++)
                ra[i] = *(const float4*)&g_barout[(long)(mBase + arow + i * 64) * HH + (kt + 1) * 16 + aq * 4];
#pragma unroll
            for (int i = 0; i < 4; i++)
                rb[i] = *(const float4*)&Wt[(long)(nBase + arow + i * 64) * HH + (kt + 1) * 16 + aq * 4];
        }
#pragma unroll
        for (int ksx = 0; ksx < 2; ksx++) {
            const float* Ab = As + ((cur * 2 + ksx) * 128) * 12;
            const float* Bb = Bs + ((cur * 2 + ksx) * 256) * 12;
            uint32_t bfr[8][2];
#pragma unroll
            for (int nf = 0; nf < 8; nf++) {
                int n = warpN + nf * 8 + g;
                bfr[nf][0] = __float_as_uint(Bb[n * 12 + kq]);
                bfr[nf][1] = __float_as_uint(Bb[n * 12 + kq + 4]);
            }
#pragma unroll
            for (int mf = 0; mf < 4; mf++) {
                int r = warpM + mf * 16 + g;
                uint32_t a[4];
                a[0] = __float_as_uint(Ab[r * 12 + kq]);
                a[1] = __float_as_uint(Ab[(r + 8) * 12 + kq]);
                a[2] = __float_as_uint(Ab[r * 12 + kq + 4]);
                a[3] = __float_as_uint(Ab[(r + 8) * 12 + kq + 4]);
#pragma unroll
                for (int nf = 0; nf < 8; nf++) mma_tf32(acc[mf][nf], a, bfr[nf]);
            }
        }
        if (kt < 63) {
            const int nxt = cur ^ 1;
#pragma unroll
            for (int i = 0; i < 2; i++) {
                float* d = &As[((nxt * 2 + (aq >> 1)) * 128 + arow + i * 64) * 12 + (aq & 1) * 4];
                d[0] = __uint_as_float(f2tf(ra[i].x)); d[1] = __uint_as_float(f2tf(ra[i].y));
                d[2] = __uint_as_float(f2tf(ra[i].z)); d[3] = __uint_as_float(f2tf(ra[i].w));
            }
#pragma unroll
            for (int i = 0; i < 4; i++) {
                float* d = &Bs[((nxt * 2 + (aq >> 1)) * 256 + arow + i * 64) * 12 + (aq & 1) * 4];
                d[0] = __uint_as_float(f2tf(rb[i].x)); d[1] = __uint_as_float(f2tf(rb[i].y));
                d[2] = __uint_as_float(f2tf(rb[i].z)); d[3] = __uint_as_float(f2tf(rb[i].w));
            }
        }
        __syncthreads();
    }

#pragma unroll
    for (int mf = 0; mf < 4; mf++) {
        int r0 = mBase + warpM + mf * 16 + g;
        int r1 = r0 + 8;
        int t0 = r0 >> 5, b0i = r0 & 31;
        int t1 = r1 >> 5, b1i = r1 & 31;
#pragma unroll
        for (int nf = 0; nf < 8; nf++) {
            int col = nBase + warpN + nf * 8 + kq * 2;
            float2 v0 = make_float2(acc[mf][nf][0] + bc0[nf], acc[mf][nf][1] + bc1[nf]);
            float2 v1 = make_float2(acc[mf][nf][2] + bc0[nf], acc[mf][nf][3] + bc1[nf]);
            *(float2*)&out[((long)b0i * TT + t0) * VV + col] = v0;
            *(float2*)&out[((long)b1i * TT + t1) * VV + col] = v1;
        }
    }
}

// ---------------- launch ----------------
extern "C" void kernel_launch(void* const* d_in, const int* in_sizes, int n_in,
                              void* d_out, int out_size) {
    const int*   inputs  = (const int*)d_in[0];
    const float* hiddens = (const float*)d_in[1];
    const float* hidden  = (const float*)d_in[2];
    const float* cell    = (const float*)d_in[3];
    const float* emb     = (const float*)d_in[4];
    const float* W_ih    = (const float*)d_in[5];
    const float* b_ih    = (const float*)d_in[6];
    const float* W_hh    = (const float*)d_in[7];
    const float* b_hh    = (const float*)d_in[8];
    const float* fc1_W   = (const float*)d_in[9];
    const float* fc1_b   = (const float*)d_in[10];
    const float* fc2_W   = (const float*)d_in[11];
    const float* fc2_b   = (const float*)d_in[12];
    float* out = (float*)d_out;

    cudaFuncSetAttribute(fc2_mma, cudaFuncAttributeMaxDynamicSharedMemorySize, 73728);

    embed_gemm<<<dim3(G4H / 128, (TT * BB) / 128), 256>>>(inputs, emb, W_ih, b_ih, b_hh);
    p_gemm<<<dim3(HH / 128, (SS * BB) / 128), 256>>>(hiddens, fc1_W);
    recurrent<<<NBLK, 256>>>(hiddens, hidden, cell, W_hh, fc1_W, fc1_b);
    fc2_mma<<<dim3(VV / 256, (TT * BB) / 128), 256, 73728>>>(fc2_W, fc2_b, out);
}

// round 4
// speedup vs baseline: 1.3559x; 1.3559x over previous
#include <cuda_runtime.h>
#include <math.h>
#include <stdint.h>

#define BB 32
#define TT 64
#define SS 64
#define HH 1024
#define EE 512
#define VV 32000
#define G4H 4096
#define BH (BB * HH)   // 32768

// ---------------- device scratch ----------------
__device__ float g_gi[TT * BB * G4H];        // x@W_ih^T + b_ih + b_hh (32MB)
__device__ float g_hall[(TT + 1) * BH];      // h history [t][b][j] (8.5MB)
__device__ float g_c[BH];
__device__ float g_lpart[8 * BB * G4H];      // lstm split-K partials (4MB)
__device__ float g_P[SS * BH];               // hiddens . fc1W_ctx  (8MB)
__device__ float g_a[BB * TT * SS];          // softmax weights [b][t][s] (512KB)
__device__ float g_barout[TT * BH];          // fc1 pre/post (8MB)

__global__ void init_hc(const float* __restrict__ h0, const float* __restrict__ c0) {
    int i = blockIdx.x * 256 + threadIdx.x;
    g_hall[i] = h0[i];
    g_c[i] = c0[i];
}

// ---------------- GEMM1: gi = emb[vid] @ W_ih^T + b_ih + b_hh ----------------
__global__ void embed_gemm(const int* __restrict__ inputs, const float* __restrict__ emb,
                           const float* __restrict__ W, const float* __restrict__ b1,
                           const float* __restrict__ b2) {
    __shared__ float As[16][128];
    __shared__ float Bs[16][128];
    __shared__ int vid[128];
    const int tid = threadIdx.x;
    const int mBase = blockIdx.y * 128, nBase = blockIdx.x * 128;
    if (tid < 128) {
        int m = mBase + tid;
        vid[tid] = inputs[(m & 31) * TT + (m >> 5)];
    }
    const int tx = tid & 15, ty = tid >> 4;
    const int lrow = tid >> 1, lcol = (tid & 1) * 8;
    float acc[8][8] = {};
    __syncthreads();
    const float* aSrc = emb + (long)vid[lrow] * EE + lcol;
    const float* bSrc = W + (long)(nBase + lrow) * EE + lcol;
    for (int k0 = 0; k0 < EE; k0 += 16) {
        float4 a0 = *(const float4*)(aSrc + k0);
        float4 a1 = *(const float4*)(aSrc + k0 + 4);
        float4 w0 = *(const float4*)(bSrc + k0);
        float4 w1 = *(const float4*)(bSrc + k0 + 4);
        As[lcol + 0][lrow] = a0.x; As[lcol + 1][lrow] = a0.y;
        As[lcol + 2][lrow] = a0.z; As[lcol + 3][lrow] = a0.w;
        As[lcol + 4][lrow] = a1.x; As[lcol + 5][lrow] = a1.y;
        As[lcol + 6][lrow] = a1.z; As[lcol + 7][lrow] = a1.w;
        Bs[lcol + 0][lrow] = w0.x; Bs[lcol + 1][lrow] = w0.y;
        Bs[lcol + 2][lrow] = w0.z; Bs[lcol + 3][lrow] = w0.w;
        Bs[lcol + 4][lrow] = w1.x; Bs[lcol + 5][lrow] = w1.y;
        Bs[lcol + 6][lrow] = w1.z; Bs[lcol + 7][lrow] = w1.w;
        __syncthreads();
#pragma unroll
        for (int k = 0; k < 16; k++) {
            float a[8], bv[8];
            *(float4*)&a[0] = *(const float4*)&As[k][ty * 8];
            *(float4*)&a[4] = *(const float4*)&As[k][ty * 8 + 4];
            *(float4*)&bv[0] = *(const float4*)&Bs[k][tx * 8];
            *(float4*)&bv[4] = *(const float4*)&Bs[k][tx * 8 + 4];
#pragma unroll
            for (int i = 0; i < 8; i++)
#pragma unroll
                for (int j = 0; j < 8; j++) acc[i][j] += a[i] * bv[j];
        }
        __syncthreads();
    }
#pragma unroll
    for (int i = 0; i < 8; i++) {
        int m = mBase + ty * 8 + i;
        float* o = g_gi + (long)m * G4H + nBase + tx * 8;
#pragma unroll
        for (int j = 0; j < 8; j++) {
            int n = nBase + tx * 8 + j;
            o[j] = acc[i][j] + b1[n] + b2[n];
        }
    }
}

// ---------------- generic 128x128 SGEMM body (A rows contiguous) -----------------
// C[m][n] = sum_k A[m][k] * B[n*ldb + off + k]  (+bias), M rows of A at aBase.
template <int KDIM>
__global__ void sgemm_rowA(const float* __restrict__ Abase, const float* __restrict__ B,
                           int ldb, int boff, const float* __restrict__ bias,
                           float* __restrict__ C, int ldc) {
    __shared__ float As[16][128];
    __shared__ float Bs[16][128];
    const int tid = threadIdx.x;
    const int mBase = blockIdx.y * 128, nBase = blockIdx.x * 128;
    const int tx = tid & 15, ty = tid >> 4;
    const int lrow = tid >> 1, lcol = (tid & 1) * 8;
    float acc[8][8] = {};
    const float* aSrc = Abase + (long)(mBase + lrow) * KDIM + lcol;
    const float* bSrc = B + (long)(nBase + lrow) * ldb + boff + lcol;
    for (int k0 = 0; k0 < KDIM; k0 += 16) {
        float4 a0 = *(const float4*)(aSrc + k0);
        float4 a1 = *(const float4*)(aSrc + k0 + 4);
        float4 w0 = *(const float4*)(bSrc + k0);
        float4 w1 = *(const float4*)(bSrc + k0 + 4);
        As[lcol + 0][lrow] = a0.x; As[lcol + 1][lrow] = a0.y;
        As[lcol + 2][lrow] = a0.z; As[lcol + 3][lrow] = a0.w;
        As[lcol + 4][lrow] = a1.x; As[lcol + 5][lrow] = a1.y;
        As[lcol + 6][lrow] = a1.z; As[lcol + 7][lrow] = a1.w;
        Bs[lcol + 0][lrow] = w0.x; Bs[lcol + 1][lrow] = w0.y;
        Bs[lcol + 2][lrow] = w0.z; Bs[lcol + 3][lrow] = w0.w;
        Bs[lcol + 4][lrow] = w1.x; Bs[lcol + 5][lrow] = w1.y;
        Bs[lcol + 6][lrow] = w1.z; Bs[lcol + 7][lrow] = w1.w;
        __syncthreads();
#pragma unroll
        for (int k = 0; k < 16; k++) {
            float a[8], bv[8];
            *(float4*)&a[0] = *(const float4*)&As[k][ty * 8];
            *(float4*)&a[4] = *(const float4*)&As[k][ty * 8 + 4];
            *(float4*)&bv[0] = *(const float4*)&Bs[k][tx * 8];
            *(float4*)&bv[4] = *(const float4*)&Bs[k][tx * 8 + 4];
#pragma unroll
            for (int i = 0; i < 8; i++)
#pragma unroll
                for (int j = 0; j < 8; j++) acc[i][j] += a[i] * bv[j];
        }
        __syncthreads();
    }
#pragma unroll
    for (int i = 0; i < 8; i++) {
        int m = mBase + ty * 8 + i;
        float* o = C + (long)m * ldc + nBase + tx * 8;
#pragma unroll
        for (int j = 0; j < 8; j++) {
            int n = nBase + tx * 8 + j;
            o[j] = acc[i][j] + (bias ? bias[n] : 0.f);
        }
    }
}

// ---------------- lstm_gemm: partial[ks][b][c] = sum_{k chunk} h[b][k] W_hh[c][k] ----
__global__ void lstm_gemm(int t, const float* __restrict__ Whh) {
    __shared__ float Hs[32][36];
    __shared__ float Ws[32][268];
    const int tid = threadIdx.x;
    const int cBase = blockIdx.x * 256;
    const int ks = blockIdx.y;
    const int kb = ks * 128;
    const float* __restrict__ hin = g_hall + (long)t * BH;
    const int b0 = (tid & 7) * 4;
    const int c0 = (tid >> 3) * 8;
    const int hb = tid >> 3, hk4 = (tid & 7) * 4;
    float acc[4][8] = {};
    for (int k0 = 0; k0 < 128; k0 += 32) {
        float4 hv = *(const float4*)&hin[hb * HH + kb + k0 + hk4];
        Hs[hk4 + 0][hb] = hv.x; Hs[hk4 + 1][hb] = hv.y;
        Hs[hk4 + 2][hb] = hv.z; Hs[hk4 + 3][hb] = hv.w;
#pragma unroll
        for (int i = 0; i < 8; i++) {
            int v = tid + i * 256;
            int c = v >> 3, k4 = (v & 7) * 4;
            float4 wv = *(const float4*)&Whh[(long)(cBase + c) * HH + kb + k0 + k4];
            Ws[k4 + 0][c] = wv.x; Ws[k4 + 1][c] = wv.y;
            Ws[k4 + 2][c] = wv.z; Ws[k4 + 3][c] = wv.w;
        }
        __syncthreads();
#pragma unroll
        for (int k = 0; k < 32; k++) {
            float4 h4 = *(const float4*)&Hs[k][b0];
            float4 wlo = *(const float4*)&Ws[k][c0];
            float4 whi = *(const float4*)&Ws[k][c0 + 4];
            float hv4[4] = {h4.x, h4.y, h4.z, h4.w};
            float wv8[8] = {wlo.x, wlo.y, wlo.z, wlo.w, whi.x, whi.y, whi.z, whi.w};
#pragma unroll
            for (int i = 0; i < 4; i++)
#pragma unroll
                for (int j = 0; j < 8; j++) acc[i][j] += hv4[i] * wv8[j];
        }
        __syncthreads();
    }
    float* po = g_lpart + (long)ks * BB * G4H;
#pragma unroll
    for (int i = 0; i < 4; i++) {
        float* row = po + (long)(b0 + i) * G4H + cBase + c0;
        *(float4*)row = make_float4(acc[i][0], acc[i][1], acc[i][2], acc[i][3]);
        *(float4*)(row + 4) = make_float4(acc[i][4], acc[i][5], acc[i][6], acc[i][7]);
    }
}

// ---------------- gate_point: reduce partials + gates -> h,c. 128 blocks x 256 ----
__global__ void gate_point(int t) {
    const int idx = blockIdx.x * 256 + threadIdx.x;  // 32768 = b*1024 + j
    const int b = idx >> 10, j = idx & 1023;
    const float* gr = g_gi + (long)(t * BB + b) * G4H;
    float xi = gr[j], xf = gr[HH + j], xg = gr[2 * HH + j], xo = gr[3 * HH + j];
#pragma unroll
    for (int ks = 0; ks < 8; ks++) {
        const float* p = g_lpart + (long)(ks * BB + b) * G4H;
        xi += p[j]; xf += p[HH + j]; xg += p[2 * HH + j]; xo += p[3 * HH + j];
    }
    float ig = 1.f / (1.f + expf(-xi));
    float fg = 1.f / (1.f + expf(-xf));
    float gg = tanhf(xg);
    float og = 1.f / (1.f + expf(-xo));
    float cn = fg * g_c[idx] + ig * gg;
    g_c[idx] = cn;
    g_hall[(long)(t + 1) * BH + idx] = og * tanhf(cn);
}

// ---------------- attn_score: scores + softmax -> g_a[b][t][s]. 32 blocks x 256 ----
__global__ void attn_score(int t, const float* __restrict__ hiddens) {
    const int b = blockIdx.x;
    __shared__ float hsh[HH];
    __shared__ float sc[SS];
    const int tid = threadIdx.x;
    const int lane = tid & 31, w = tid >> 5;
    const float* __restrict__ h = g_hall + (long)(t + 1) * BH + b * HH;
    *(float4*)&hsh[tid * 4] = *(const float4*)&h[tid * 4];
    __syncthreads();
#pragma unroll
    for (int si = 0; si < 8; si++) {
        int s = w * 8 + si;
        const float* e = hiddens + ((long)s * BB + b) * HH;
        float a = 0.f;
#pragma unroll
        for (int r = 0; r < 8; r++) {
            float4 ev = *(const float4*)&e[lane * 4 + r * 128];
            float4 h4 = *(const float4*)&hsh[lane * 4 + r * 128];
            a += ev.x * h4.x + ev.y * h4.y + ev.z * h4.z + ev.w * h4.w;
        }
        for (int o = 16; o; o >>= 1) a += __shfl_down_sync(0xFFFFFFFFu, a, o);
        if (!lane) sc[s] = a;
    }
    __syncthreads();
    if (tid < 32) {
        float v0 = sc[tid], v1 = sc[tid + 32];
        float m = fmaxf(v0, v1);
        for (int o = 16; o; o >>= 1) m = fmaxf(m, __shfl_xor_sync(0xFFFFFFFFu, m, o));
        float e0 = expf(v0 - m), e1 = expf(v1 - m);
        float s = e0 + e1;
        for (int o = 16; o; o >>= 1) s += __shfl_xor_sync(0xFFFFFFFFu, s, o);
        float inv = 1.f / s;
        float* ao = g_a + ((long)b * TT + t) * SS;
        ao[tid] = e0 * inv;
        ao[tid + 32] = e1 * inv;
    }
}

// ---------------- ctxp_tanh: barout += a @ P (per b), then tanh. grid (8, 32) -------
__global__ void __launch_bounds__(256) ctxp_tanh() {
    __shared__ float As[TT * SS];        // a[t][s] 16KB
    __shared__ float Ps[SS * 128];       // P[s][j] 32KB
    const int tid = threadIdx.x;
    const int b = blockIdx.y;
    const int jbase = blockIdx.x * 128;
    // load a tile
#pragma unroll
    for (int i = 0; i < 4; i++) {
        int v4 = tid + i * 256;
        *(float4*)&As[v4 * 4] = *(const float4*)&g_a[(long)b * TT * SS + v4 * 4];
    }
    // load P tile
#pragma unroll
    for (int i = 0; i < 8; i++) {
        int v4 = tid + i * 256;            // 2048 float4s
        int s = v4 >> 5, j4 = v4 & 31;
        *(float4*)&Ps[s * 128 + j4 * 4] =
            *(const float4*)&g_P[((long)s * BB + b) * HH + jbase + j4 * 4];
    }
    __syncthreads();
    const int tq = tid >> 5;            // 8 t-groups of 8
    const int j0 = (tid & 31) * 4;
    float acc[8][4] = {};
    for (int s = 0; s < SS; s++) {
        float4 pv = *(const float4*)&Ps[s * 128 + j0];
#pragma unroll
        for (int i = 0; i < 8; i++) {
            float av = As[(tq * 8 + i) * SS + s];
            acc[i][0] += av * pv.x; acc[i][1] += av * pv.y;
            acc[i][2] += av * pv.z; acc[i][3] += av * pv.w;
        }
    }
#pragma unroll
    for (int i = 0; i < 8; i++) {
        int tt = tq * 8 + i;
        float* o = g_barout + ((long)tt * BB + b) * HH + jbase + j0;
        float4 pre = *(const float4*)o;
        pre.x = tanhf(pre.x + acc[i][0]);
        pre.y = tanhf(pre.y + acc[i][1]);
        pre.z = tanhf(pre.z + acc[i][2]);
        pre.w = tanhf(pre.w + acc[i][3]);
        *(float4*)o = pre;
    }
}

// ---------------- fc2: tf32 mma.sync GEMM. M=2048, N=32000, K=1024 ----------------
__device__ __forceinline__ uint32_t f2tf(float x) {
    uint32_t r;
    asm("cvt.rna.tf32.f32 %0, %1;" : "=r"(r) : "f"(x));
    return r;
}
__device__ __forceinline__ void mma_tf32(float* c, const uint32_t* a, const uint32_t* b) {
    asm volatile(
        "mma.sync.aligned.m16n8k8.row.col.f32.tf32.tf32.f32 "
        "{%0,%1,%2,%3},{%4,%5,%6,%7},{%8,%9},{%0,%1,%2,%3};"
        : "+f"(c[0]), "+f"(c[1]), "+f"(c[2]), "+f"(c[3])
        : "r"(a[0]), "r"(a[1]), "r"(a[2]), "r"(a[3]), "r"(b[0]), "r"(b[1]));
}

__global__ void __launch_bounds__(256) fc2_mma(const float* __restrict__ Wt,
                                               const float* __restrict__ bias,
                                               float* __restrict__ out) {
    extern __shared__ float smem[];
    float* As = smem;            // [2buf][2ks][128][12]
    float* Bs = smem + 6144;     // [2buf][2ks][256][12]
    const int tid = threadIdx.x;
    const int wid = tid >> 5, lane = tid & 31;
    const int g = lane >> 2, kq = lane & 3;
    const int mBase = blockIdx.y * 128;
    const int nBase = blockIdx.x * 256;
    const int warpM = (wid & 1) * 64;
    const int warpN = (wid >> 1) * 64;

    float acc[4][8][4];
#pragma unroll
    for (int i = 0; i < 4; i++)
#pragma unroll
        for (int j = 0; j < 8; j++)
#pragma unroll
            for (int k = 0; k < 4; k++) acc[i][j][k] = 0.f;

    float bc0[8], bc1[8];
#pragma unroll
    for (int nf = 0; nf < 8; nf++) {
        int col = nBase + warpN + nf * 8 + kq * 2;
        bc0[nf] = bias[col]; bc1[nf] = bias[col + 1];
    }

    const int arow = tid >> 2, aq = tid & 3;
    {
#pragma unroll
        for (int i = 0; i < 2; i++) {
            float4 v = *(const float4*)&g_barout[(long)(mBase + arow + i * 64) * HH + aq * 4];
            float* d = &As[((0 * 2 + (aq >> 1)) * 128 + arow + i * 64) * 12 + (aq & 1) * 4];
            d[0] = __uint_as_float(f2tf(v.x)); d[1] = __uint_as_float(f2tf(v.y));
            d[2] = __uint_as_float(f2tf(v.z)); d[3] = __uint_as_float(f2tf(v.w));
        }
#pragma unroll
        for (int i = 0; i < 4; i++) {
            float4 v = *(const float4*)&Wt[(long)(nBase + arow + i * 64) * HH + aq * 4];
            float* d = &Bs[((0 * 2 + (aq >> 1)) * 256 + arow + i * 64) * 12 + (aq & 1) * 4];
            d[0] = __uint_as_float(f2tf(v.x)); d[1] = __uint_as_float(f2tf(v.y));
            d[2] = __uint_as_float(f2tf(v.z)); d[3] = __uint_as_float(f2tf(v.w));
        }
    }
    __syncthreads();

    float4 ra[2], rb[4];
    for (int kt = 0; kt < 64; kt++) {
        const int cur = kt & 1;
        if (kt < 63) {
#pragma unroll
            for (int i = 0; i < 2; i++)
                ra[i] = *(const float4*)&g_barout[(long)(mBase + arow + i * 64) * HH + (kt + 1) * 16 + aq * 4];
#pragma unroll
            for (int i = 0; i < 4; i++)
                rb[i] = *(const float4*)&Wt[(long)(nBase + arow + i * 64) * HH + (kt + 1) * 16 + aq * 4];
        }
#pragma unroll
        for (int ksx = 0; ksx < 2; ksx++) {
            const float* Ab = As + ((cur * 2 + ksx) * 128) * 12;
            const float* Bb = Bs + ((cur * 2 + ksx) * 256) * 12;
            uint32_t bfr[8][2];
#pragma unroll
            for (int nf = 0; nf < 8; nf++) {
                int n = warpN + nf * 8 + g;
                bfr[nf][0] = __float_as_uint(Bb[n * 12 + kq]);
                bfr[nf][1] = __float_as_uint(Bb[n * 12 + kq + 4]);
            }
#pragma unroll
            for (int mf = 0; mf < 4; mf++) {
                int r = warpM + mf * 16 + g;
                uint32_t a[4];
                a[0] = __float_as_uint(Ab[r * 12 + kq]);
                a[1] = __float_as_uint(Ab[(r + 8) * 12 + kq]);
                a[2] = __float_as_uint(Ab[r * 12 + kq + 4]);
                a[3] = __float_as_uint(Ab[(r + 8) * 12 + kq + 4]);
#pragma unroll
                for (int nf = 0; nf < 8; nf++) mma_tf32(acc[mf][nf], a, bfr[nf]);
            }
        }
        if (kt < 63) {
            const int nxt = cur ^ 1;
#pragma unroll
            for (int i = 0; i < 2; i++) {
                float* d = &As[((nxt * 2 + (aq >> 1)) * 128 + arow + i * 64) * 12 + (aq & 1) * 4];
                d[0] = __uint_as_float(f2tf(ra[i].x)); d[1] = __uint_as_float(f2tf(ra[i].y));
                d[2] = __uint_as_float(f2tf(ra[i].z)); d[3] = __uint_as_float(f2tf(ra[i].w));
            }
#pragma unroll
            for (int i = 0; i < 4; i++) {
                float* d = &Bs[((nxt * 2 + (aq >> 1)) * 256 + arow + i * 64) * 12 + (aq & 1) * 4];
                d[0] = __uint_as_float(f2tf(rb[i].x)); d[1] = __uint_as_float(f2tf(rb[i].y));
                d[2] = __uint_as_float(f2tf(rb[i].z)); d[3] = __uint_as_float(f2tf(rb[i].w));
            }
        }
        __syncthreads();
    }

#pragma unroll
    for (int mf = 0; mf < 4; mf++) {
        int r0 = mBase + warpM + mf * 16 + g;
        int r1 = r0 + 8;
        int t0 = r0 >> 5, b0i = r0 & 31;
        int t1 = r1 >> 5, b1i = r1 & 31;
#pragma unroll
        for (int nf = 0; nf < 8; nf++) {
            int col = nBase + warpN + nf * 8 + kq * 2;
            float2 v0 = make_float2(acc[mf][nf][0] + bc0[nf], acc[mf][nf][1] + bc1[nf]);
            float2 v1 = make_float2(acc[mf][nf][2] + bc0[nf], acc[mf][nf][3] + bc1[nf]);
            *(float2*)&out[((long)b0i * TT + t0) * VV + col] = v0;
            *(float2*)&out[((long)b1i * TT + t1) * VV + col] = v1;
        }
    }
}

// ---------------- launch ----------------
extern "C" void kernel_launch(void* const* d_in, const int* in_sizes, int n_in,
                              void* d_out, int out_size) {
    const int*   inputs  = (const int*)d_in[0];
    const float* hiddens = (const float*)d_in[1];
    const float* hidden  = (const float*)d_in[2];
    const float* cell    = (const float*)d_in[3];
    const float* emb     = (const float*)d_in[4];
    const float* W_ih    = (const float*)d_in[5];
    const float* b_ih    = (const float*)d_in[6];
    const float* W_hh    = (const float*)d_in[7];
    const float* b_hh    = (const float*)d_in[8];
    const float* fc1_W   = (const float*)d_in[9];
    const float* fc1_b   = (const float*)d_in[10];
    const float* fc2_W   = (const float*)d_in[11];
    const float* fc2_b   = (const float*)d_in[12];
    float* out = (float*)d_out;

    cudaFuncSetAttribute(fc2_mma, cudaFuncAttributeMaxDynamicSharedMemorySize, 73728);

    float* g_hall_p; cudaGetSymbolAddress((void**)&g_hall_p, g_hall);
    float* g_P_p;    cudaGetSymbolAddress((void**)&g_P_p, g_P);
    float* g_bar_p;  cudaGetSymbolAddress((void**)&g_bar_p, g_barout);

    init_hc<<<128, 256>>>(hidden, cell);
    embed_gemm<<<dim3(G4H / 128, (TT * BB) / 128), 256>>>(inputs, emb, W_ih, b_ih, b_hh);
    // P[s*32+b][j] = hiddens row . fc1_W[j][1024:2048]
    sgemm_rowA<HH><<<dim3(HH / 128, (SS * BB) / 128), 256>>>(
        hiddens, fc1_W, 2048, 1024, nullptr, g_P_p, HH);
    for (int t = 0; t < TT; t++) {
        lstm_gemm<<<dim3(16, 8), 256>>>(t, W_hh);
        gate_point<<<128, 256>>>(t);
        attn_score<<<BB, 256>>>(t, hiddens);
    }
    // fc1 h-part: barout[m][j] = hall[m+32] . fc1_W[j][0:1024] + fc1_b
    sgemm_rowA<HH><<<dim3(HH / 128, (TT * BB) / 128), 256>>>(
        g_hall_p + BH, fc1_W, 2048, 0, fc1_b, g_bar_p, HH);
    ctxp_tanh<<<dim3(8, BB), 256>>>();
    fc2_mma<<<dim3(VV / 256, (TT * BB) / 128), 256, 73728>>>(fc2_W, fc2_b, out);
}